// round 6
// baseline (speedup 1.0000x reference)
#include <cuda_runtime.h>
#include <cuda_fp16.h>

#define B_ 32
#define N_ 65536
#define CHUNKS 32          // blocks per batch in pass1
#define TPB 256

// Deterministic per-block partials: [b][block][27]  (21 sym H_eff + 6 g_eff)
__device__ float g_part[B_][CHUNKS][27];

// Per-point scratch, 16 bytes: ti[6] as 3x half2, s as fp32.
// ti = inv_H_dd * H_pd (only ever dotted with the 6-vector dp -> fp16-safe),
// s  = inv_H_dd * g_d  (sets the output scale -> keep fp32).
struct __align__(16) Scr { __half2 t01, t23, t45; float s; };
__device__ Scr g_scratch[(size_t)B_ * N_];

// ---------------------------------------------------------------------------
// Pass 1: single sweep over inputs (streaming/evict-first loads). Accumulates
// the Schur-reduced 6x6 system per batch in fp32 and writes 16B/point scratch.
// ---------------------------------------------------------------------------
__global__ __launch_bounds__(TPB) void pass1_kernel(
    const float* __restrict__ r, const float* __restrict__ w,
    const float* __restrict__ Jp, const float* __restrict__ Jd,
    const float* __restrict__ lmbda)
{
    const int b = blockIdx.y;
    const float lam = __ldg(lmbda);

    float acc[27];
#pragma unroll
    for (int v = 0; v < 27; v++) acc[v] = 0.f;

    const int   gtid   = blockIdx.x * TPB + threadIdx.x;
    const int   stride = CHUNKS * TPB;
    const size_t base2  = (size_t)b * N_ * 2;
    const size_t base12 = (size_t)b * N_ * 12;

    for (int n = gtid; n < N_; n += stride) {
        float2 rv = __ldcs((const float2*)(r  + base2 + 2 * (size_t)n));
        float2 wv = __ldcs((const float2*)(w  + base2 + 2 * (size_t)n));
        float2 dv = __ldcs((const float2*)(Jd + base2 + 2 * (size_t)n));
        const float4* jp4 = (const float4*)(Jp + base12 + 12 * (size_t)n);
        float4 a0 = __ldcs(jp4 + 0), a1 = __ldcs(jp4 + 1), a2 = __ldcs(jp4 + 2);
        float p0[6] = {a0.x, a0.y, a0.z, a0.w, a1.x, a1.y};
        float p1[6] = {a1.z, a1.w, a2.x, a2.y, a2.z, a2.w};

        const float wd0 = wv.x * dv.x, wd1 = wv.y * dv.y;   // w*Jd per k
        const float wr0 = wv.x * rv.x, wr1 = wv.y * rv.y;   // w*r  per k

        const float Hdd = dv.x * wd0 + dv.y * wd1 + lam;    // sum_k Jd^2 w + lambda
        const float gd  = rv.x * wd0 + rv.y * wd1;          // sum_k Jd w r
        const float inv = 1.f / (Hdd + 1e-8f);
        const float s   = inv * gd;

        float hpd[6], ti[6];
#pragma unroll
        for (int i = 0; i < 6; i++) {
            hpd[i] = p0[i] * wd0 + p1[i] * wd1;             // H_pd_i
            ti[i]  = hpd[i] * inv;
        }

        // 16B compressed scratch (single STG.128)
        Scr sc;
        sc.t01 = __floats2half2_rn(ti[0], ti[1]);
        sc.t23 = __floats2half2_rn(ti[2], ti[3]);
        sc.t45 = __floats2half2_rn(ti[4], ti[5]);
        sc.s   = s;
        g_scratch[(size_t)b * N_ + n] = sc;

        int c = 0;
#pragma unroll
        for (int i = 0; i < 6; i++) {
            const float qi0 = p0[i] * wv.x, qi1 = p1[i] * wv.y;
#pragma unroll
            for (int j = i; j < 6; j++, c++)
                acc[c] += qi0 * p0[j] + qi1 * p1[j] - ti[i] * hpd[j];
            acc[21 + i] += p0[i] * wr0 + p1[i] * wr1 - hpd[i] * s;
        }
    }

    // warp reduce all 27
#pragma unroll
    for (int v = 0; v < 27; v++)
#pragma unroll
        for (int off = 16; off; off >>= 1)
            acc[v] += __shfl_down_sync(0xffffffffu, acc[v], off);

    __shared__ float swarp[TPB / 32][27];
    const int wid = threadIdx.x >> 5, lid = threadIdx.x & 31;
    if (lid == 0) {
#pragma unroll
        for (int v = 0; v < 27; v++) swarp[wid][v] = acc[v];
    }
    __syncthreads();
    if (threadIdx.x < 27) {
        float s = 0.f;
#pragma unroll
        for (int wv = 0; wv < TPB / 32; wv++) s += swarp[wv][threadIdx.x];
        g_part[b][blockIdx.x][threadIdx.x] = s;  // deterministic, no atomics
    }
}

// ---------------------------------------------------------------------------
// Pass 2 (fused solve, ONE wave): 128 fat blocks (4 per batch). Each block
// pays the g_part reduction + serial 6x6 SPD solve exactly once, then streams
// 16384 points. Prologue is concurrent across blocks instead of repeated
// across 7 block-waves per SM.
// ---------------------------------------------------------------------------
#define P2_BLOCKS 4                  // blocks per batch  -> 128 total (1 wave)
#define P2_PTS   (N_ / P2_BLOCKS)    // 16384 points per block
#define P2_ITERS (P2_PTS / 256)      // 64 points per thread

__global__ __launch_bounds__(256) void pass2_kernel(
    const float* __restrict__ lmbda, float* __restrict__ out)
{
    const int b = blockIdx.y;
    __shared__ float s27[27];
    __shared__ float dp[6];

    if (threadIdx.x < 27) {
        float s = 0.f;
#pragma unroll
        for (int c = 0; c < CHUNKS; c++) s += g_part[b][c][threadIdx.x];
        s27[threadIdx.x] = s;
    }
    __syncthreads();

    if (threadIdx.x == 0) {
        const float lam = __ldg(lmbda);
        float A[6][7];
        int c = 0;
#pragma unroll
        for (int i = 0; i < 6; i++)
#pragma unroll
            for (int j = i; j < 6; j++, c++) { A[i][j] = s27[c]; A[j][i] = s27[c]; }
#pragma unroll
        for (int i = 0; i < 6; i++) {
            A[i][i] += lam + 1e-4f;      // lambda*I (H_pp) + eps*I (H_eff)
            A[i][6]  = s27[21 + i];      // g_eff
        }
        // no-pivot Gaussian elimination (SPD: Schur complement + (lam+eps)I)
#pragma unroll
        for (int col = 0; col < 6; col++) {
            const float pinv = 1.f / A[col][col];
#pragma unroll
            for (int rr = 0; rr < 6; rr++) {
                if (rr > col) {
                    const float f = A[rr][col] * pinv;
#pragma unroll
                    for (int j = 0; j < 7; j++)
                        if (j >= col) A[rr][j] -= f * A[col][j];
                }
            }
        }
        float x[6];
#pragma unroll
        for (int ii = 5; ii >= 0; ii--) {
            float s = A[ii][6];
#pragma unroll
            for (int j = 0; j < 6; j++)
                if (j > ii) s -= A[ii][j] * x[j];
            x[ii] = s / A[ii][ii];
        }
#pragma unroll
        for (int i = 0; i < 6; i++) dp[i] = x[i];
    }
    __syncthreads();

    if (blockIdx.x == 0 && threadIdx.x < 6)
        out[b * 6 + threadIdx.x] = dp[threadIdx.x];

    float* depth = out + B_ * 6;
    const float d0 = dp[0], d1 = dp[1], d2 = dp[2];
    const float d3 = dp[3], d4 = dp[4], d5 = dp[5];
    const int base = blockIdx.x * P2_PTS;

#pragma unroll 8
    for (int i = 0; i < P2_ITERS; i++) {
        const int n = base + threadIdx.x + i * 256;
        const uint4 raw = __ldcs((const uint4*)(g_scratch + (size_t)b * N_ + n));
        Scr sc;
        *(uint4*)&sc = raw;
        const float2 f01 = __half22float2(sc.t01);
        const float2 f23 = __half22float2(sc.t23);
        const float2 f45 = __half22float2(sc.t45);
        float v = sc.s - (f01.x * d0 + f01.y * d1 + f23.x * d2 +
                          f23.y * d3 + f45.x * d4 + f45.y * d5);
        __stcs(depth + (size_t)b * N_ + n, v);
    }
}

// ---------------------------------------------------------------------------
extern "C" void kernel_launch(void* const* d_in, const int* in_sizes, int n_in,
                              void* d_out, int out_size)
{
    const float* r  = (const float*)d_in[0];
    const float* w  = (const float*)d_in[1];
    const float* Jp = (const float*)d_in[2];
    const float* Jd = (const float*)d_in[3];
    const float* lm = (const float*)d_in[4];

    float* out = (float*)d_out;    // [B,6] pose then [B,N] depth

    dim3 g1(CHUNKS, B_);
    pass1_kernel<<<g1, TPB>>>(r, w, Jp, Jd, lm);
    dim3 g2(P2_BLOCKS, B_);
    pass2_kernel<<<g2, 256>>>(lm, out);
}